// round 9
// baseline (speedup 1.0000x reference)
#include <cuda_runtime.h>
#include <cuda_bf16.h>
#include <stdint.h>

// ---------------------------------------------------------------------------
// Problem constants
// ---------------------------------------------------------------------------
#define N_NODES 1024
#define NN      8192        // BATCH(64) * F(128)
#define OUT_DIM 128
#define PLANE   (N_NODES * NN)   // 8,388,608 elements

// Global scratch. Split-bf16: value ~= hi + lo (error ~2^-17 relative)
__device__ __align__(16) __nv_bfloat16 g_AsH[2][N_NODES * N_NODES];
__device__ __align__(16) __nv_bfloat16 g_AsL[2][N_NODES * N_NODES];
__device__ __align__(16) __nv_bfloat16 g_XnH[5][PLANE];  // node-major [node][col]
__device__ __align__(16) __nv_bfloat16 g_XnL[5][PLANE];
__device__ __align__(16) __nv_bfloat16 g_WtH[5][128 * 128]; // Wt[m][o][f]
__device__ __align__(16) __nv_bfloat16 g_WtL[5][128 * 128];

// ---------------------------------------------------------------------------
// PTX helpers
// ---------------------------------------------------------------------------
__device__ __forceinline__ uint32_t smem_u32(const void* p) {
    uint32_t a;
    asm("{ .reg .u64 t; cvta.to.shared.u64 t, %1; cvt.u32.u64 %0, t; }" : "=r"(a) : "l"(p));
    return a;
}
__device__ __forceinline__ void cp16(uint32_t dst, const void* src) {
    asm volatile("cp.async.cg.shared.global [%0], [%1], 16;" :: "r"(dst), "l"(src));
}
__device__ __forceinline__ void cp_commit() {
    asm volatile("cp.async.commit_group;" ::: "memory");
}
__device__ __forceinline__ void cp_wait1() {
    asm volatile("cp.async.wait_group 1;" ::: "memory");
}
__device__ __forceinline__ void ldsm4(uint32_t& r0, uint32_t& r1, uint32_t& r2, uint32_t& r3,
                                      uint32_t addr) {
    asm volatile("ldmatrix.sync.aligned.m8n8.x4.shared.b16 {%0,%1,%2,%3}, [%4];"
                 : "=r"(r0), "=r"(r1), "=r"(r2), "=r"(r3) : "r"(addr));
}
__device__ __forceinline__ void ldsm4t(uint32_t& r0, uint32_t& r1, uint32_t& r2, uint32_t& r3,
                                       uint32_t addr) {
    asm volatile("ldmatrix.sync.aligned.m8n8.x4.trans.shared.b16 {%0,%1,%2,%3}, [%4];"
                 : "=r"(r0), "=r"(r1), "=r"(r2), "=r"(r3) : "r"(addr));
}
__device__ __forceinline__ void mma16816(float* c, const uint32_t* a, const uint32_t* b) {
    asm volatile(
        "mma.sync.aligned.m16n8k16.row.col.f32.bf16.bf16.f32 "
        "{%0,%1,%2,%3}, {%4,%5,%6,%7}, {%8,%9}, {%0,%1,%2,%3};"
        : "+f"(c[0]), "+f"(c[1]), "+f"(c[2]), "+f"(c[3])
        : "r"(a[0]), "r"(a[1]), "r"(a[2]), "r"(a[3]), "r"(b[0]), "r"(b[1]));
}

__device__ __forceinline__ uint32_t packbf2(__nv_bfloat16 a, __nv_bfloat16 b) {
    __nv_bfloat162 t; t.x = a; t.y = b;
    return *reinterpret_cast<uint32_t*>(&t);
}
__device__ __forceinline__ void split2(float x, float y, uint32_t& h, uint32_t& l) {
    __nv_bfloat16 hx = __float2bfloat16(x);
    __nv_bfloat16 hy = __float2bfloat16(y);
    __nv_bfloat16 lx = __float2bfloat16(x - __bfloat162float(hx));
    __nv_bfloat16 ly = __float2bfloat16(y - __bfloat162float(hy));
    h = packbf2(hx, hy);
    l = packbf2(lx, ly);
}

// ---------------------------------------------------------------------------
// SMEM layouts
// A planes: [rows][32 k] bf16, pitch 80 B (conflict-free non-trans ldmatrix;
//   20r mod 32 words distinct per 8-row phase)
// Diffusion B planes: [32 k][256 n] bf16, pitch 528 B (132 words ≡ 4 mod 32 —
//   same conflict-free residue as the proven 68-word pitch)
// ---------------------------------------------------------------------------
#define A_PITCH 80
#define A64_PLANE  (64 * A_PITCH)        // 5120 B
#define A128_PLANE (128 * A_PITCH)       // 10240 B
#define B_PITCH 528
#define B_PLANE (32 * B_PITCH)           // 16896 B

// Diffusion stage (CTA tile 128m x 256n, BK=32): Ah, Al (128-row), Bh, Bl
#define D_OFF_AH 0
#define D_OFF_AL A128_PLANE
#define D_OFF_BH (2 * A128_PLANE)
#define D_OFF_BL (2 * A128_PLANE + B_PLANE)
#define D_STAGE  (2 * A128_PLANE + 2 * B_PLANE)   // 54272 B
#define D_TOTAL  (3 * D_STAGE)                    // 162816 B

// Final stage (M-tile 64, 256 threads): Xh, Xl (64-row), Wh, Wl (128-row)
#define F_OFF_XH 0
#define F_OFF_XL A64_PLANE
#define F_OFF_WH (2 * A64_PLANE)
#define F_OFF_WL (2 * A64_PLANE + A128_PLANE)
#define F_STAGE  (2 * A64_PLANE + 2 * A128_PLANE)  // 30720 B
#define F_TOTAL  (3 * F_STAGE)                     // 92160 B

// [64 x 32] tile -> pitch-80 plane; 256 threads, 1 cp16 each
__device__ __forceinline__ void issue_rows64(uint32_t smp, const __nv_bfloat16* src,
                                             int strideElems, int tid) {
    int row = tid >> 2;
    int ch  = tid & 3;
    cp16(smp + row * A_PITCH + ch * 16,
         (const char*)(src + (size_t)row * strideElems) + ch * 16);
}
// [128 x 32] tile -> pitch-80 plane; 256 threads, 2 cp16 each
__device__ __forceinline__ void issue_rows128_t256(uint32_t smp, const __nv_bfloat16* src,
                                                   int strideElems, int tid) {
    #pragma unroll
    for (int j = 0; j < 2; j++) {
        int id  = tid + j * 256;
        int row = id >> 2;
        int ch  = id & 3;
        cp16(smp + row * A_PITCH + ch * 16,
             (const char*)(src + (size_t)row * strideElems) + ch * 16);
    }
}
// [128 x 32] tile -> pitch-80 plane; 512 threads, 1 cp16 each
__device__ __forceinline__ void issue_rows128_t512(uint32_t smp, const __nv_bfloat16* src,
                                                   int strideElems, int tid) {
    int row = tid >> 2;
    int ch  = tid & 3;
    cp16(smp + row * A_PITCH + ch * 16,
         (const char*)(src + (size_t)row * strideElems) + ch * 16);
}
// [32 k x 256 n] tile -> pitch-528 plane; 512 threads, 2 cp16 each
__device__ __forceinline__ void issue_plane_b256(uint32_t smp, const __nv_bfloat16* src,
                                                 int strideElems, int tid) {
    #pragma unroll
    for (int j = 0; j < 2; j++) {
        int id  = tid + j * 512;
        int row = id >> 5;          // 0..31 (k)
        int ch  = id & 31;          // 0..31 (16B chunks across 256 n)
        cp16(smp + row * B_PITCH + ch * 16,
             (const char*)(src + (size_t)row * strideElems) + ch * 16);
    }
}

// ---------------------------------------------------------------------------
// Diffusion GEMM: D[node][col] = alpha * sum_k A[node][k] * X[k][col] - prev
// CTA tile 128 x 256, 512 threads = 16 warps (4 m x 4 n), warp tile 32 x 64.
// Grid (32 colTiles, 8 nodeTiles, 2 supports) = 512 CTAs, 1 CTA/SM.
// ---------------------------------------------------------------------------
__global__ void __launch_bounds__(512, 1)
gemm_cheby_mma(int step) {
    extern __shared__ __align__(128) char smem[];
    uint32_t sb = smem_u32(smem);
    int tid = threadIdx.x;
    int colTile  = blockIdx.x * 256;
    int nodeTile = blockIdx.y * 128;
    int s = blockIdx.z;

    int srcN  = (step == 0) ? 0 : (1 + 2 * s);
    int prevN = (step == 0) ? -1 : 0;
    int dstN  = (step == 0) ? (1 + 2 * s) : (2 + 2 * s);
    float alpha = (step == 0) ? 1.0f : 2.0f;

    const __nv_bfloat16* Ah = g_AsH[s] + (size_t)nodeTile * N_NODES;
    const __nv_bfloat16* Al = g_AsL[s] + (size_t)nodeTile * N_NODES;
    const __nv_bfloat16* Bh = g_XnH[srcN] + colTile;   // row index = k (node)
    const __nv_bfloat16* Bl = g_XnL[srcN] + colTile;

    const int NIT = N_NODES / 32;   // 32

    #pragma unroll
    for (int p = 0; p < 2; p++) {
        uint32_t st = sb + p * D_STAGE;
        int k0 = p * 32;
        issue_rows128_t512(st + D_OFF_AH, Ah + k0, N_NODES, tid);
        issue_rows128_t512(st + D_OFF_AL, Al + k0, N_NODES, tid);
        issue_plane_b256(st + D_OFF_BH, Bh + (size_t)k0 * NN, NN, tid);
        issue_plane_b256(st + D_OFF_BL, Bl + (size_t)k0 * NN, NN, tid);
        cp_commit();
    }

    int wid = tid >> 5, lane = tid & 31;
    int wm = wid >> 2, wn = wid & 3;
    int m0 = wm * 32;                       // warp M origin (2 x 16-row frags)
    int n0 = wn * 64;                       // warp N origin (8 x 8-col frags)
    int a_row  = m0 + (lane & 7) + ((lane >> 3) & 1) * 8;
    int a_byte = (lane >> 4) * 16;
    int b_krow  = lane & 15;
    int b_nbyte = (lane >> 4) * 16;

    float acc[2][8][4] = {};

    for (int it = 0; it < NIT; it++) {
        cp_wait1();
        __syncthreads();
        if (it + 2 < NIT) {
            uint32_t st = sb + ((it + 2) % 3) * D_STAGE;
            int k0 = (it + 2) * 32;
            issue_rows128_t512(st + D_OFF_AH, Ah + k0, N_NODES, tid);
            issue_rows128_t512(st + D_OFF_AL, Al + k0, N_NODES, tid);
            issue_plane_b256(st + D_OFF_BH, Bh + (size_t)k0 * NN, NN, tid);
            issue_plane_b256(st + D_OFF_BL, Bl + (size_t)k0 * NN, NN, tid);
        }
        cp_commit();

        uint32_t st = sb + (it % 3) * D_STAGE;
        #pragma unroll
        for (int ks = 0; ks < 2; ks++) {
            uint32_t ah[2][4], al[2][4];
            #pragma unroll
            for (int mt = 0; mt < 2; mt++) {
                uint32_t ad = st + D_OFF_AH + (uint32_t)(a_row + mt * 16) * A_PITCH
                              + ks * 32 + a_byte;
                ldsm4(ah[mt][0], ah[mt][1], ah[mt][2], ah[mt][3], ad);
                ldsm4(al[mt][0], al[mt][1], al[mt][2], al[mt][3], ad + A128_PLANE);
            }
            // two n-halves of 32 cols each to bound live registers
            #pragma unroll
            for (int half = 0; half < 2; half++) {
                uint32_t bh[4][2], bl[4][2];
                #pragma unroll
                for (int np = 0; np < 2; np++) {
                    uint32_t bd = st + D_OFF_BH + (uint32_t)(ks * 16 + b_krow) * B_PITCH
                                  + (uint32_t)(n0 + half * 32 + np * 16) * 2 + b_nbyte;
                    uint32_t t0, t1, t2, t3;
                    ldsm4t(t0, t1, t2, t3, bd);
                    bh[2 * np][0] = t0; bh[2 * np][1] = t1;
                    bh[2 * np + 1][0] = t2; bh[2 * np + 1][1] = t3;
                    ldsm4t(t0, t1, t2, t3, bd + B_PLANE);
                    bl[2 * np][0] = t0; bl[2 * np][1] = t1;
                    bl[2 * np + 1][0] = t2; bl[2 * np + 1][1] = t3;
                }
                #pragma unroll
                for (int mt = 0; mt < 2; mt++)
                    #pragma unroll
                    for (int nt = 0; nt < 4; nt++)
                        mma16816(acc[mt][half * 4 + nt], ah[mt], bh[nt]);
                #pragma unroll
                for (int mt = 0; mt < 2; mt++)
                    #pragma unroll
                    for (int nt = 0; nt < 4; nt++)
                        mma16816(acc[mt][half * 4 + nt], ah[mt], bl[nt]);
                #pragma unroll
                for (int mt = 0; mt < 2; mt++)
                    #pragma unroll
                    for (int nt = 0; nt < 4; nt++)
                        mma16816(acc[mt][half * 4 + nt], al[mt], bh[nt]);
            }
        }
    }

    // Epilogue: v = alpha*acc - (prevH+prevL); write split node-major.
    int l4 = lane >> 2, lp = lane & 3;
    #pragma unroll
    for (int mt = 0; mt < 2; mt++) {
        #pragma unroll
        for (int nt = 0; nt < 8; nt++) {
            int col = colTile + n0 + nt * 8 + lp * 2;
            #pragma unroll
            for (int h = 0; h < 2; h++) {
                int node = nodeTile + m0 + mt * 16 + l4 + h * 8;
                float vx = alpha * acc[mt][nt][h * 2 + 0];
                float vy = alpha * acc[mt][nt][h * 2 + 1];
                size_t off = (size_t)node * NN + col;
                if (prevN >= 0) {
                    __nv_bfloat162 ph = *reinterpret_cast<const __nv_bfloat162*>(&g_XnH[prevN][off]);
                    __nv_bfloat162 pl = *reinterpret_cast<const __nv_bfloat162*>(&g_XnL[prevN][off]);
                    vx -= __bfloat162float(ph.x) + __bfloat162float(pl.x);
                    vy -= __bfloat162float(ph.y) + __bfloat162float(pl.y);
                }
                uint32_t hp, lpk;
                split2(vx, vy, hp, lpk);
                *reinterpret_cast<uint32_t*>(&g_XnH[dstN][off]) = hp;
                *reinterpret_cast<uint32_t*>(&g_XnL[dstN][off]) = lpk;
            }
        }
    }
}

// ---------------------------------------------------------------------------
// Final projection: out[r][o] = sum_m sum_f Xn[m][r][f]*Wt[m][o][f] + bias
// M-tile 64, 256 threads (8 warps 2m x 4n, warp tile 32 x 32). Grid 1024.
// (unchanged from the passing round-8 config)
// ---------------------------------------------------------------------------
__global__ void __launch_bounds__(256, 2)
final_gemm_mma(const float* __restrict__ biases, float* __restrict__ out) {
    extern __shared__ __align__(128) char smem[];
    uint32_t sb = smem_u32(smem);
    int tid = threadIdx.x;
    int rTile = blockIdx.x * 64;

    const int NIT = 20;   // 5 planes x 4 k-chunks of 32

    #pragma unroll
    for (int p = 0; p < 2; p++) {
        uint32_t st = sb + p * F_STAGE;
        int m = p >> 2, f0 = (p & 3) * 32;
        issue_rows64    (st + F_OFF_XH, g_XnH[m] + (size_t)rTile * 128 + f0, 128, tid);
        issue_rows64    (st + F_OFF_XL, g_XnL[m] + (size_t)rTile * 128 + f0, 128, tid);
        issue_rows128_t256(st + F_OFF_WH, g_WtH[m] + f0, 128, tid);
        issue_rows128_t256(st + F_OFF_WL, g_WtL[m] + f0, 128, tid);
        cp_commit();
    }

    int wid = tid >> 5, lane = tid & 31;
    int wm = wid >> 2, wn = wid & 3;
    int m0 = wm * 32, n0 = wn * 32;
    int a_row  = m0 + (lane & 7) + ((lane >> 3) & 1) * 8;
    int a_byte = (lane >> 4) * 16;
    int b_row  = n0 + ((lane >> 4) << 3) + (lane & 7);
    int b_byte = ((lane >> 3) & 1) * 16;

    float acc[2][4][4] = {};

    for (int it = 0; it < NIT; it++) {
        cp_wait1();
        __syncthreads();
        if (it + 2 < NIT) {
            int nx = it + 2;
            uint32_t st = sb + (nx % 3) * F_STAGE;
            int m = nx >> 2, f0 = (nx & 3) * 32;
            issue_rows64    (st + F_OFF_XH, g_XnH[m] + (size_t)rTile * 128 + f0, 128, tid);
            issue_rows64    (st + F_OFF_XL, g_XnL[m] + (size_t)rTile * 128 + f0, 128, tid);
            issue_rows128_t256(st + F_OFF_WH, g_WtH[m] + f0, 128, tid);
            issue_rows128_t256(st + F_OFF_WL, g_WtL[m] + f0, 128, tid);
        }
        cp_commit();

        uint32_t st = sb + (it % 3) * F_STAGE;
        #pragma unroll
        for (int ks = 0; ks < 2; ks++) {
            uint32_t ah[2][4], al[2][4], bh[4][2], bl[4][2];
            #pragma unroll
            for (int mt = 0; mt < 2; mt++) {
                uint32_t ad = st + F_OFF_XH + (uint32_t)(a_row + mt * 16) * A_PITCH
                              + ks * 32 + a_byte;
                ldsm4(ah[mt][0], ah[mt][1], ah[mt][2], ah[mt][3], ad);
                ldsm4(al[mt][0], al[mt][1], al[mt][2], al[mt][3], ad + A64_PLANE);
            }
            #pragma unroll
            for (int np = 0; np < 2; np++) {
                uint32_t bd = st + F_OFF_WH +
                              (uint32_t)(b_row + np * 16) * A_PITCH + ks * 32 + b_byte;
                uint32_t t0, t1, t2, t3;
                ldsm4(t0, t1, t2, t3, bd);
                bh[2 * np][0] = t0; bh[2 * np][1] = t1;
                bh[2 * np + 1][0] = t2; bh[2 * np + 1][1] = t3;
                ldsm4(t0, t1, t2, t3, bd + A128_PLANE);
                bl[2 * np][0] = t0; bl[2 * np][1] = t1;
                bl[2 * np + 1][0] = t2; bl[2 * np + 1][1] = t3;
            }
            #pragma unroll
            for (int mt = 0; mt < 2; mt++)
                #pragma unroll
                for (int nt = 0; nt < 4; nt++)
                    mma16816(acc[mt][nt], ah[mt], bh[nt]);
            #pragma unroll
            for (int mt = 0; mt < 2; mt++)
                #pragma unroll
                for (int nt = 0; nt < 4; nt++)
                    mma16816(acc[mt][nt], ah[mt], bl[nt]);
            #pragma unroll
            for (int mt = 0; mt < 2; mt++)
                #pragma unroll
                for (int nt = 0; nt < 4; nt++)
                    mma16816(acc[mt][nt], al[mt], bh[nt]);
        }
    }

    int l4 = lane >> 2, lp = lane & 3;
    #pragma unroll
    for (int mt = 0; mt < 2; mt++) {
        #pragma unroll
        for (int nt = 0; nt < 4; nt++) {
            int o = n0 + nt * 8 + lp * 2;
            float b0 = biases[o], b1 = biases[o + 1];
            #pragma unroll
            for (int h = 0; h < 2; h++) {
                int r = rTile + m0 + mt * 16 + l4 + h * 8;
                int b = r & 63, n = r >> 6;
                float2 v;
                v.x = acc[mt][nt][h * 2 + 0] + b0;
                v.y = acc[mt][nt][h * 2 + 1] + b1;
                *reinterpret_cast<float2*>(&out[(size_t)b * (N_NODES * OUT_DIM) + n * OUT_DIM + o]) = v;
            }
        }
    }
}

// ---------------------------------------------------------------------------
// Prep kernels
// ---------------------------------------------------------------------------
__global__ void split_supports(const float* __restrict__ sup) {
    int idx = blockIdx.x * blockDim.x + threadIdx.x;   // float4 index, 524288 total
    float4 v = reinterpret_cast<const float4*>(sup)[idx];
    uint32_t h0, l0, h1, l1;
    split2(v.x, v.y, h0, l0);
    split2(v.z, v.w, h1, l1);
    reinterpret_cast<uint2*>(&g_AsH[0][0])[idx] = make_uint2(h0, h1);
    reinterpret_cast<uint2*>(&g_AsL[0][0])[idx] = make_uint2(l0, l1);
}

__global__ void build_x0_split(const float* __restrict__ inputs,
                               const float* __restrict__ state) {
    int idx = blockIdx.x * blockDim.x + threadIdx.x;   // float4 index, 2097152 total
    int f4 = idx & 31;
    int b  = (idx >> 5) & 63;
    int n  = idx >> 11;
    float4 v;
    if (f4 < 16)
        v = reinterpret_cast<const float4*>(inputs)[b * 16384 + n * 16 + f4];
    else
        v = reinterpret_cast<const float4*>(state )[b * 16384 + n * 16 + (f4 - 16)];
    uint32_t h0, l0, h1, l1;
    split2(v.x, v.y, h0, l0);
    split2(v.z, v.w, h1, l1);
    reinterpret_cast<uint2*>(&g_XnH[0][0])[idx] = make_uint2(h0, h1);
    reinterpret_cast<uint2*>(&g_XnL[0][0])[idx] = make_uint2(l0, l1);
}

// Wt[m][o][f] = weight[(f*5+m)][o], split
__global__ void prep_w_split(const float* __restrict__ wsrc) {
    int idx = blockIdx.x * blockDim.x + threadIdx.x;   // 81920 total
    int m = idx / 16384;
    int rem = idx % 16384;
    int o = rem / 128;
    int f = rem % 128;
    float v = wsrc[(f * 5 + m) * 128 + o];
    __nv_bfloat16 h = __float2bfloat16(v);
    __nv_bfloat16 l = __float2bfloat16(v - __bfloat162float(h));
    g_WtH[0][idx] = h;
    g_WtL[0][idx] = l;
}

// ---------------------------------------------------------------------------
// Launch
// ---------------------------------------------------------------------------
extern "C" void kernel_launch(void* const* d_in, const int* in_sizes, int n_in,
                              void* d_out, int out_size) {
    const float* supports = (const float*)d_in[0];  // [2,1024,1024]
    const float* inputs   = (const float*)d_in[1];  // [64, 65536]
    const float* state    = (const float*)d_in[2];  // [64, 65536]
    const float* weight   = (const float*)d_in[3];  // [640, 128]
    const float* biases   = (const float*)d_in[4];  // [128]
    float* out = (float*)d_out;                     // [64, 131072]

    cudaFuncSetAttribute(gemm_cheby_mma, cudaFuncAttributeMaxDynamicSharedMemorySize, D_TOTAL);
    cudaFuncSetAttribute(final_gemm_mma, cudaFuncAttributeMaxDynamicSharedMemorySize, F_TOTAL);

    split_supports<<<2048, 256>>>(supports);
    build_x0_split<<<8192, 256>>>(inputs, state);
    prep_w_split<<<320, 256>>>(weight);

    dim3 gd(NN / 256, N_NODES / 128, 2);   // (32, 8, 2) = 512 CTAs
    gemm_cheby_mma<<<gd, 512, D_TOTAL>>>(0);   // x1_s = A_s @ x0
    gemm_cheby_mma<<<gd, 512, D_TOTAL>>>(1);   // x2_s = 2*A_s @ x1_s - x0

    final_gemm_mma<<<1024, 256, F_TOTAL>>>(biases, out);
}

// round 11
// speedup vs baseline: 1.1965x; 1.1965x over previous
#include <cuda_runtime.h>
#include <cuda_bf16.h>
#include <stdint.h>

// ---------------------------------------------------------------------------
// Problem constants
// ---------------------------------------------------------------------------
#define N_NODES 1024
#define NN      8192        // BATCH(64) * F(128)
#define OUT_DIM 128
#define PLANE   (N_NODES * NN)   // 8,388,608 elements

// Global scratch. Split-bf16: value ~= hi + lo (error ~2^-17 relative)
__device__ __align__(16) __nv_bfloat16 g_AsH[2][N_NODES * N_NODES];
__device__ __align__(16) __nv_bfloat16 g_AsL[2][N_NODES * N_NODES];
__device__ __align__(16) __nv_bfloat16 g_XnH[5][PLANE];  // node-major [node][col]
__device__ __align__(16) __nv_bfloat16 g_XnL[5][PLANE];
__device__ __align__(16) __nv_bfloat16 g_WtH[5][128 * 128]; // Wt[m][o][f]
__device__ __align__(16) __nv_bfloat16 g_WtL[5][128 * 128];

// Persistent-kernel sync state: [0] = ticket, [2 + s*64 + c] = column counters.
// Zeroed every launch by build_x0_split (stream-ordered before the GEMM).
__device__ int g_sync[132];

// ---------------------------------------------------------------------------
// PTX helpers (sm_80-compatible: cp.async + ldmatrix + mma.sync bf16)
// ---------------------------------------------------------------------------
__device__ __forceinline__ uint32_t smem_u32(const void* p) {
    uint32_t a;
    asm("{ .reg .u64 t; cvta.to.shared.u64 t, %1; cvt.u32.u64 %0, t; }" : "=r"(a) : "l"(p));
    return a;
}
__device__ __forceinline__ void cp16(uint32_t dst, const void* src) {
    asm volatile("cp.async.cg.shared.global [%0], [%1], 16;" :: "r"(dst), "l"(src));
}
__device__ __forceinline__ void cp_commit() {
    asm volatile("cp.async.commit_group;" ::: "memory");
}
__device__ __forceinline__ void cp_wait1() {
    asm volatile("cp.async.wait_group 1;" ::: "memory");
}
__device__ __forceinline__ void ldsm4(uint32_t& r0, uint32_t& r1, uint32_t& r2, uint32_t& r3,
                                      uint32_t addr) {
    asm volatile("ldmatrix.sync.aligned.m8n8.x4.shared.b16 {%0,%1,%2,%3}, [%4];"
                 : "=r"(r0), "=r"(r1), "=r"(r2), "=r"(r3) : "r"(addr));
}
__device__ __forceinline__ void ldsm4t(uint32_t& r0, uint32_t& r1, uint32_t& r2, uint32_t& r3,
                                       uint32_t addr) {
    asm volatile("ldmatrix.sync.aligned.m8n8.x4.trans.shared.b16 {%0,%1,%2,%3}, [%4];"
                 : "=r"(r0), "=r"(r1), "=r"(r2), "=r"(r3) : "r"(addr));
}
__device__ __forceinline__ void mma16816(float* c, const uint32_t* a, const uint32_t* b) {
    asm volatile(
        "mma.sync.aligned.m16n8k16.row.col.f32.bf16.bf16.f32 "
        "{%0,%1,%2,%3}, {%4,%5,%6,%7}, {%8,%9}, {%0,%1,%2,%3};"
        : "+f"(c[0]), "+f"(c[1]), "+f"(c[2]), "+f"(c[3])
        : "r"(a[0]), "r"(a[1]), "r"(a[2]), "r"(a[3]), "r"(b[0]), "r"(b[1]));
}

__device__ __forceinline__ uint32_t packbf2(__nv_bfloat16 a, __nv_bfloat16 b) {
    __nv_bfloat162 t; t.x = a; t.y = b;
    return *reinterpret_cast<uint32_t*>(&t);
}
__device__ __forceinline__ void split2(float x, float y, uint32_t& h, uint32_t& l) {
    __nv_bfloat16 hx = __float2bfloat16(x);
    __nv_bfloat16 hy = __float2bfloat16(y);
    __nv_bfloat16 lx = __float2bfloat16(x - __bfloat162float(hx));
    __nv_bfloat16 ly = __float2bfloat16(y - __bfloat162float(hy));
    h = packbf2(hx, hy);
    l = packbf2(lx, ly);
}

// ---------------------------------------------------------------------------
// SMEM layouts (R8 config — the best measured inner loop)
// A planes: [rows][32 k] bf16, pitch 80 B (conflict-free non-trans ldmatrix)
// B planes: [32 k][128 n] bf16, pitch 272 B (conflict-free trans ldmatrix)
// ---------------------------------------------------------------------------
#define A_PITCH 80
#define A64_PLANE  (64 * A_PITCH)        // 5120 B
#define A128_PLANE (128 * A_PITCH)       // 10240 B
#define B_PITCH 272
#define B_PLANE (32 * B_PITCH)           // 8704 B

// Diffusion stage (CTA tile 128m x 128n, BK=32): Ah, Al (128-row), Bh, Bl (trans)
#define D_OFF_AH 0
#define D_OFF_AL A128_PLANE
#define D_OFF_BH (2 * A128_PLANE)
#define D_OFF_BL (2 * A128_PLANE + B_PLANE)
#define D_STAGE  (2 * A128_PLANE + 2 * B_PLANE)   // 37888 B
#define D_TOTAL  (3 * D_STAGE)                    // 113664 B

// Final stage (M-tile 64): Xh, Xl (64-row), Wh, Wl (128-row)
#define F_OFF_XH 0
#define F_OFF_XL A64_PLANE
#define F_OFF_WH (2 * A64_PLANE)
#define F_OFF_WL (2 * A64_PLANE + A128_PLANE)
#define F_STAGE  (2 * A64_PLANE + 2 * A128_PLANE)  // 30720 B
#define F_TOTAL  (3 * F_STAGE)                     // 92160 B

// [64 x 32] tile -> pitch-80 plane; 256 threads, 1 cp16 each
__device__ __forceinline__ void issue_rows64(uint32_t smp, const __nv_bfloat16* src,
                                             int strideElems, int tid) {
    int row = tid >> 2;
    int ch  = tid & 3;
    cp16(smp + row * A_PITCH + ch * 16,
         (const char*)(src + (size_t)row * strideElems) + ch * 16);
}
// [128 x 32] tile -> pitch-80 plane; 256 threads, 2 cp16 each
__device__ __forceinline__ void issue_rows128(uint32_t smp, const __nv_bfloat16* src,
                                              int strideElems, int tid) {
    #pragma unroll
    for (int j = 0; j < 2; j++) {
        int id  = tid + j * 256;
        int row = id >> 2;
        int ch  = id & 3;
        cp16(smp + row * A_PITCH + ch * 16,
             (const char*)(src + (size_t)row * strideElems) + ch * 16);
    }
}
// [32 k x 128 n] tile -> pitch-272 plane; 256 threads, 2 cp16 each
__device__ __forceinline__ void issue_plane_b(uint32_t smp, const __nv_bfloat16* src,
                                              int strideElems, int tid) {
    #pragma unroll
    for (int j = 0; j < 2; j++) {
        int id  = tid + j * 256;
        int row = id >> 4;          // 0..31 (k)
        int ch  = id & 15;          // 0..15 (16B chunks across 128 n)
        cp16(smp + row * B_PITCH + ch * 16,
             (const char*)(src + (size_t)row * strideElems) + ch * 16);
    }
}

// ---------------------------------------------------------------------------
// Persistent diffusion GEMM.
// Work units ("tiles"): 2048 total, ticket-ordered.
//   phase1 (t in [0,1024)):   x1_s = A_s @ x0            (no prev, alpha 1)
//   phase2 (t in [1024,2048)): x2_s = 2*A_s @ x1_s - x0  (prev x0, alpha 2)
// Decode: c = (t mod 1024) >> 4 (column strip), r = t & 15, s = r >> 3, m = r & 7.
// Column-grouped order: tickets 0-15 complete column strip 0 for both supports,
// unblocking phase2 col 0 early. Counter g_sync[2 + s*64 + c] counts the 8
// producer tiles of (s, c); phase2 consumers acquire-spin to 8.
// Deadlock-free: any spinning CTA holds a ticket > all phase1 tickets, which
// are therefore all grabbed and being executed by resident CTAs.
// ---------------------------------------------------------------------------
#define N_TILES_PHASE 1024
#define N_TILES_TOTAL 2048

__global__ void __launch_bounds__(256, 2)
gemm_cheby_persist() {
    extern __shared__ __align__(128) char smem[];
    __shared__ int s_ticket;
    uint32_t sb = smem_u32(smem);
    int tid = threadIdx.x;

    int wid = tid >> 5, lane = tid & 31;
    int wm = wid >> 2, wn = wid & 3;
    int m0 = wm * 64;
    int n0 = wn * 32;
    int a_row  = m0 + (lane & 7) + ((lane >> 3) & 1) * 8;
    int a_byte = (lane >> 4) * 16;
    int b_krow  = lane & 15;
    int b_nbyte = (lane >> 4) * 16;
    int l4 = lane >> 2, lp = lane & 3;

    for (;;) {
        if (tid == 0) s_ticket = atomicAdd(&g_sync[0], 1);
        __syncthreads();            // broadcast ticket; also separates prior
                                    // tile's compute from new cp.async writes
        int t = s_ticket;
        if (t >= N_TILES_TOTAL) break;

        int phase2 = (t >= N_TILES_PHASE);
        int u = phase2 ? (t - N_TILES_PHASE) : t;
        int c = u >> 4;             // 0..63 column strip
        int r = u & 15;
        int s = r >> 3;             // support
        int m = r & 7;              // node tile
        int colTile  = c * 128;
        int nodeTile = m * 128;

        int srcN  = phase2 ? (1 + 2 * s) : 0;
        int prevN = phase2 ? 0 : -1;
        int dstN  = phase2 ? (2 + 2 * s) : (1 + 2 * s);
        float alpha = phase2 ? 2.0f : 1.0f;

        // phase2: wait for all 8 producer tiles of (s, c)
        if (phase2) {
            if (tid == 0) {
                int v;
                do {
                    asm volatile("ld.acquire.gpu.global.b32 %0, [%1];"
                                 : "=r"(v) : "l"(&g_sync[2 + s * 64 + c]) : "memory");
                    if (v < 8) __nanosleep(64);
                } while (v < 8);
            }
            __syncthreads();
        }

        const __nv_bfloat16* Ah = g_AsH[s] + (size_t)nodeTile * N_NODES;
        const __nv_bfloat16* Al = g_AsL[s] + (size_t)nodeTile * N_NODES;
        const __nv_bfloat16* Bh = g_XnH[srcN] + colTile;   // row index = k (node)
        const __nv_bfloat16* Bl = g_XnL[srcN] + colTile;

        const int NIT = N_NODES / 32;   // 32

        #pragma unroll
        for (int p = 0; p < 2; p++) {
            uint32_t st = sb + p * D_STAGE;
            int k0 = p * 32;
            issue_rows128(st + D_OFF_AH, Ah + k0, N_NODES, tid);
            issue_rows128(st + D_OFF_AL, Al + k0, N_NODES, tid);
            issue_plane_b(st + D_OFF_BH, Bh + (size_t)k0 * NN, NN, tid);
            issue_plane_b(st + D_OFF_BL, Bl + (size_t)k0 * NN, NN, tid);
            cp_commit();
        }

        float acc[4][4][4] = {};

        for (int it = 0; it < NIT; it++) {
            cp_wait1();
            __syncthreads();
            if (it + 2 < NIT) {
                uint32_t st = sb + ((it + 2) % 3) * D_STAGE;
                int k0 = (it + 2) * 32;
                issue_rows128(st + D_OFF_AH, Ah + k0, N_NODES, tid);
                issue_rows128(st + D_OFF_AL, Al + k0, N_NODES, tid);
                issue_plane_b(st + D_OFF_BH, Bh + (size_t)k0 * NN, NN, tid);
                issue_plane_b(st + D_OFF_BL, Bl + (size_t)k0 * NN, NN, tid);
            }
            cp_commit();

            uint32_t st = sb + (it % 3) * D_STAGE;
            #pragma unroll
            for (int ks = 0; ks < 2; ks++) {
                uint32_t ah[4][4], al[4][4], bh[4][2], bl[4][2];
                #pragma unroll
                for (int mt = 0; mt < 4; mt++) {
                    uint32_t ad = st + D_OFF_AH + (uint32_t)(a_row + mt * 16) * A_PITCH
                                  + ks * 32 + a_byte;
                    ldsm4(ah[mt][0], ah[mt][1], ah[mt][2], ah[mt][3], ad);
                    ldsm4(al[mt][0], al[mt][1], al[mt][2], al[mt][3], ad + A128_PLANE);
                }
                #pragma unroll
                for (int np = 0; np < 2; np++) {
                    uint32_t bd = st + D_OFF_BH + (uint32_t)(ks * 16 + b_krow) * B_PITCH
                                  + (uint32_t)(n0 + np * 16) * 2 + b_nbyte;
                    uint32_t t0, t1, t2, t3;
                    ldsm4t(t0, t1, t2, t3, bd);
                    bh[2 * np][0] = t0; bh[2 * np][1] = t1;
                    bh[2 * np + 1][0] = t2; bh[2 * np + 1][1] = t3;
                    ldsm4t(t0, t1, t2, t3, bd + B_PLANE);
                    bl[2 * np][0] = t0; bl[2 * np][1] = t1;
                    bl[2 * np + 1][0] = t2; bl[2 * np + 1][1] = t3;
                }
                #pragma unroll
                for (int mt = 0; mt < 4; mt++)
                    #pragma unroll
                    for (int nt = 0; nt < 4; nt++)
                        mma16816(acc[mt][nt], ah[mt], bh[nt]);
                #pragma unroll
                for (int mt = 0; mt < 4; mt++)
                    #pragma unroll
                    for (int nt = 0; nt < 4; nt++)
                        mma16816(acc[mt][nt], ah[mt], bl[nt]);
                #pragma unroll
                for (int mt = 0; mt < 4; mt++)
                    #pragma unroll
                    for (int nt = 0; nt < 4; nt++)
                        mma16816(acc[mt][nt], al[mt], bh[nt]);
            }
        }

        // Epilogue: v = alpha*acc - (prevH+prevL); write split node-major.
        #pragma unroll
        for (int mt = 0; mt < 4; mt++) {
            #pragma unroll
            for (int nt = 0; nt < 4; nt++) {
                int col = colTile + n0 + nt * 8 + lp * 2;
                #pragma unroll
                for (int h = 0; h < 2; h++) {
                    int node = nodeTile + m0 + mt * 16 + l4 + h * 8;
                    float vx = alpha * acc[mt][nt][h * 2 + 0];
                    float vy = alpha * acc[mt][nt][h * 2 + 1];
                    size_t off = (size_t)node * NN + col;
                    if (prevN >= 0) {
                        __nv_bfloat162 ph = *reinterpret_cast<const __nv_bfloat162*>(&g_XnH[prevN][off]);
                        __nv_bfloat162 pl = *reinterpret_cast<const __nv_bfloat162*>(&g_XnL[prevN][off]);
                        vx -= __bfloat162float(ph.x) + __bfloat162float(pl.x);
                        vy -= __bfloat162float(ph.y) + __bfloat162float(pl.y);
                    }
                    uint32_t hp, lpk;
                    split2(vx, vy, hp, lpk);
                    *reinterpret_cast<uint32_t*>(&g_XnH[dstN][off]) = hp;
                    *reinterpret_cast<uint32_t*>(&g_XnL[dstN][off]) = lpk;
                }
            }
        }

        // Publish (phase1) — release the stores to phase2 consumers.
        __threadfence();
        __syncthreads();
        if (!phase2 && tid == 0)
            atomicAdd(&g_sync[2 + s * 64 + c], 1);
    }
}

// ---------------------------------------------------------------------------
// Final projection: out[r][o] = sum_m sum_f Xn[m][r][f]*Wt[m][o][f] + bias
// M-tile 64, 256 threads (8 warps 2m x 4n, warp tile 32 x 32). Grid 1024.
// (unchanged from the passing round-8 config)
// ---------------------------------------------------------------------------
__global__ void __launch_bounds__(256, 2)
final_gemm_mma(const float* __restrict__ biases, float* __restrict__ out) {
    extern __shared__ __align__(128) char smem[];
    uint32_t sb = smem_u32(smem);
    int tid = threadIdx.x;
    int rTile = blockIdx.x * 64;

    const int NIT = 20;   // 5 planes x 4 k-chunks of 32

    #pragma unroll
    for (int p = 0; p < 2; p++) {
        uint32_t st = sb + p * F_STAGE;
        int m = p >> 2, f0 = (p & 3) * 32;
        issue_rows64 (st + F_OFF_XH, g_XnH[m] + (size_t)rTile * 128 + f0, 128, tid);
        issue_rows64 (st + F_OFF_XL, g_XnL[m] + (size_t)rTile * 128 + f0, 128, tid);
        issue_rows128(st + F_OFF_WH, g_WtH[m] + f0, 128, tid);
        issue_rows128(st + F_OFF_WL, g_WtL[m] + f0, 128, tid);
        cp_commit();
    }

    int wid = tid >> 5, lane = tid & 31;
    int wm = wid >> 2, wn = wid & 3;
    int m0 = wm * 32, n0 = wn * 32;
    int a_row  = m0 + (lane & 7) + ((lane >> 3) & 1) * 8;
    int a_byte = (lane >> 4) * 16;
    int b_row  = n0 + ((lane >> 4) << 3) + (lane & 7);
    int b_byte = ((lane >> 3) & 1) * 16;

    float acc[2][4][4] = {};

    for (int it = 0; it < NIT; it++) {
        cp_wait1();
        __syncthreads();
        if (it + 2 < NIT) {
            int nx = it + 2;
            uint32_t st = sb + (nx % 3) * F_STAGE;
            int m = nx >> 2, f0 = (nx & 3) * 32;
            issue_rows64 (st + F_OFF_XH, g_XnH[m] + (size_t)rTile * 128 + f0, 128, tid);
            issue_rows64 (st + F_OFF_XL, g_XnL[m] + (size_t)rTile * 128 + f0, 128, tid);
            issue_rows128(st + F_OFF_WH, g_WtH[m] + f0, 128, tid);
            issue_rows128(st + F_OFF_WL, g_WtL[m] + f0, 128, tid);
        }
        cp_commit();

        uint32_t st = sb + (it % 3) * F_STAGE;
        #pragma unroll
        for (int ks = 0; ks < 2; ks++) {
            uint32_t ah[2][4], al[2][4], bh[4][2], bl[4][2];
            #pragma unroll
            for (int mt = 0; mt < 2; mt++) {
                uint32_t ad = st + F_OFF_XH + (uint32_t)(a_row + mt * 16) * A_PITCH
                              + ks * 32 + a_byte;
                ldsm4(ah[mt][0], ah[mt][1], ah[mt][2], ah[mt][3], ad);
                ldsm4(al[mt][0], al[mt][1], al[mt][2], al[mt][3], ad + A64_PLANE);
            }
            #pragma unroll
            for (int np = 0; np < 2; np++) {
                uint32_t bd = st + F_OFF_WH +
                              (uint32_t)(b_row + np * 16) * A_PITCH + ks * 32 + b_byte;
                uint32_t t0, t1, t2, t3;
                ldsm4(t0, t1, t2, t3, bd);
                bh[2 * np][0] = t0; bh[2 * np][1] = t1;
                bh[2 * np + 1][0] = t2; bh[2 * np + 1][1] = t3;
                ldsm4(t0, t1, t2, t3, bd + A128_PLANE);
                bl[2 * np][0] = t0; bl[2 * np][1] = t1;
                bl[2 * np + 1][0] = t2; bl[2 * np + 1][1] = t3;
            }
            #pragma unroll
            for (int mt = 0; mt < 2; mt++)
                #pragma unroll
                for (int nt = 0; nt < 4; nt++)
                    mma16816(acc[mt][nt], ah[mt], bh[nt]);
            #pragma unroll
            for (int mt = 0; mt < 2; mt++)
                #pragma unroll
                for (int nt = 0; nt < 4; nt++)
                    mma16816(acc[mt][nt], ah[mt], bl[nt]);
            #pragma unroll
            for (int mt = 0; mt < 2; mt++)
                #pragma unroll
                for (int nt = 0; nt < 4; nt++)
                    mma16816(acc[mt][nt], al[mt], bh[nt]);
        }
    }

    int l4 = lane >> 2, lp = lane & 3;
    #pragma unroll
    for (int mt = 0; mt < 2; mt++) {
        #pragma unroll
        for (int nt = 0; nt < 4; nt++) {
            int o = n0 + nt * 8 + lp * 2;
            float b0 = biases[o], b1 = biases[o + 1];
            #pragma unroll
            for (int h = 0; h < 2; h++) {
                int r = rTile + m0 + mt * 16 + l4 + h * 8;
                int b = r & 63, n = r >> 6;
                float2 v;
                v.x = acc[mt][nt][h * 2 + 0] + b0;
                v.y = acc[mt][nt][h * 2 + 1] + b1;
                *reinterpret_cast<float2*>(&out[(size_t)b * (N_NODES * OUT_DIM) + n * OUT_DIM + o]) = v;
            }
        }
    }
}

// ---------------------------------------------------------------------------
// Prep kernels
// ---------------------------------------------------------------------------
__global__ void split_supports(const float* __restrict__ sup) {
    int idx = blockIdx.x * blockDim.x + threadIdx.x;   // float4 index, 524288 total
    float4 v = reinterpret_cast<const float4*>(sup)[idx];
    uint32_t h0, l0, h1, l1;
    split2(v.x, v.y, h0, l0);
    split2(v.z, v.w, h1, l1);
    reinterpret_cast<uint2*>(&g_AsH[0][0])[idx] = make_uint2(h0, h1);
    reinterpret_cast<uint2*>(&g_AsL[0][0])[idx] = make_uint2(l0, l1);
}

__global__ void build_x0_split(const float* __restrict__ inputs,
                               const float* __restrict__ state) {
    int idx = blockIdx.x * blockDim.x + threadIdx.x;   // float4 index, 2097152 total
    if (idx < 132) g_sync[idx] = 0;   // reset persistent-kernel sync state
    int f4 = idx & 31;
    int b  = (idx >> 5) & 63;
    int n  = idx >> 11;
    float4 v;
    if (f4 < 16)
        v = reinterpret_cast<const float4*>(inputs)[b * 16384 + n * 16 + f4];
    else
        v = reinterpret_cast<const float4*>(state )[b * 16384 + n * 16 + (f4 - 16)];
    uint32_t h0, l0, h1, l1;
    split2(v.x, v.y, h0, l0);
    split2(v.z, v.w, h1, l1);
    reinterpret_cast<uint2*>(&g_XnH[0][0])[idx] = make_uint2(h0, h1);
    reinterpret_cast<uint2*>(&g_XnL[0][0])[idx] = make_uint2(l0, l1);
}

// Wt[m][o][f] = weight[(f*5+m)][o], split
__global__ void prep_w_split(const float* __restrict__ wsrc) {
    int idx = blockIdx.x * blockDim.x + threadIdx.x;   // 81920 total
    int m = idx / 16384;
    int rem = idx % 16384;
    int o = rem / 128;
    int f = rem % 128;
    float v = wsrc[(f * 5 + m) * 128 + o];
    __nv_bfloat16 h = __float2bfloat16(v);
    __nv_bfloat16 l = __float2bfloat16(v - __bfloat162float(h));
    g_WtH[0][idx] = h;
    g_WtL[0][idx] = l;
}

// ---------------------------------------------------------------------------
// Launch
// ---------------------------------------------------------------------------
extern "C" void kernel_launch(void* const* d_in, const int* in_sizes, int n_in,
                              void* d_out, int out_size) {
    const float* supports = (const float*)d_in[0];  // [2,1024,1024]
    const float* inputs   = (const float*)d_in[1];  // [64, 65536]
    const float* state    = (const float*)d_in[2];  // [64, 65536]
    const float* weight   = (const float*)d_in[3];  // [640, 128]
    const float* biases   = (const float*)d_in[4];  // [128]
    float* out = (float*)d_out;                     // [64, 131072]

    cudaFuncSetAttribute(gemm_cheby_persist, cudaFuncAttributeMaxDynamicSharedMemorySize, D_TOTAL);
    cudaFuncSetAttribute(final_gemm_mma, cudaFuncAttributeMaxDynamicSharedMemorySize, F_TOTAL);

    split_supports<<<2048, 256>>>(supports);
    build_x0_split<<<8192, 256>>>(inputs, state);
    prep_w_split<<<320, 256>>>(weight);

    // Persistent diffusion: 2 CTAs/SM x 148 SMs. Deadlock-free for any
    // residency (see kernel comment), so a fixed 296 is safe.
    gemm_cheby_persist<<<296, 256, D_TOTAL>>>();

    final_gemm_mma<<<1024, 256, F_TOTAL>>>(biases, out);
}